// round 1
// baseline (speedup 1.0000x reference)
#include <cuda_runtime.h>
#include <cstddef>

// Problem constants
#define BB 8
#define TT 40
#define HH 32
#define WW 32
#define CC 64
#define CM 32          // C_MVF
#define ROWS 4         // h-rows per block
#define THREADS 256

// Smem row: transposed [ci(32)][pos(34: -1..32)] layout, pitch 34 floats.
// Conflict-free for both the load transpose (warp = fixed pos, ci 0..31)
// and compute reads (warp = fixed ci, consecutive pos).
#define ROWF (32 * 34)              // 1088 floats per row
#define NROWS 14                    // 6 center-t rows (h0-1..h0+4) + 4 (t-1) + 4 (t+1)
#define WFL (7 * 32 * 32)           // 7 combined taps, [tap][ci][co]
#define SMEM_FLOATS (NROWS * ROWF + WFL)   // 22400 floats = 89600 B

__device__ __forceinline__ void load_row(float* dst, const float* __restrict__ x,
                                         int b, int t, int h, int tid) {
    if (t < 0 || t >= TT || h < 0 || h >= HH) {
        for (int j = tid; j < ROWF; j += THREADS) dst[j] = 0.0f;
        return;
    }
    // zero the W halos (pos index 0 and 33) for all 32 channels
    if (tid < 64) dst[(tid & 31) * 34 + (tid >> 5) * 33] = 0.0f;
    const float* src = x + ((((size_t)b * TT + t) * HH + h) * (size_t)WW) * CC;
    int ci = tid & 31;
    int w0 = tid >> 5;               // 0..7
#pragma unroll
    for (int p = 0; p < 4; ++p) {
        int w = w0 + p * 8;          // warp reads 128B contiguous per (pos) step
        dst[ci * 34 + w + 1] = src[(size_t)w * CC + ci];
    }
}

__global__ __launch_bounds__(THREADS, 2)
void mvf_kernel(const float* __restrict__ x,
                const float* __restrict__ wT,
                const float* __restrict__ wH,
                const float* __restrict__ wW,
                float* __restrict__ out) {
    extern __shared__ float smem[];
    float* sx = smem;                 // 14 rows
    float* sw = smem + NROWS * ROWF;  // 7*32*32 weights, [tap][ci][co]

    const int tid = threadIdx.x;
    const int bx  = blockIdx.x;
    const int ht   = bx & 7;          // H/ROWS = 8 tiles
    const int rest = bx >> 3;
    const int t    = rest % TT;
    const int b    = rest / TT;
    const int h0   = ht * ROWS;

    // ---- weights: combine into 7 taps ----
    {
        const float4* wT4 = (const float4*)wT;
        const float4* wH4 = (const float4*)wH;
        const float4* wW4 = (const float4*)wW;
        float4* sw4 = (float4*)sw;
        int r = tid;                  // 256 float4 per 32x32 tile
        sw4[0 * 256 + r] = wT4[0 * 256 + r];   // t-1
        sw4[1 * 256 + r] = wT4[2 * 256 + r];   // t+1
        sw4[2 * 256 + r] = wH4[0 * 256 + r];   // h-1
        sw4[3 * 256 + r] = wH4[2 * 256 + r];   // h+1
        sw4[4 * 256 + r] = wW4[0 * 256 + r];   // w-1
        sw4[5 * 256 + r] = wW4[2 * 256 + r];   // w+1
        float4 a = wT4[256 + r], c = wH4[256 + r], d = wW4[256 + r];
        sw4[6 * 256 + r] = make_float4(a.x + c.x + d.x, a.y + c.y + d.y,
                                       a.z + c.z + d.z, a.w + c.w + d.w);  // center
    }

    // ---- input rows ----
#pragma unroll
    for (int r = 0; r < 6; ++r)        // center-t slab: h0-1 .. h0+4
        load_row(sx + r * ROWF, x, b, t, h0 - 1 + r, tid);
#pragma unroll
    for (int q = 0; q < ROWS; ++q)     // t-1 slab
        load_row(sx + (6 + q) * ROWF, x, b, t - 1, h0 + q, tid);
#pragma unroll
    for (int q = 0; q < ROWS; ++q)     // t+1 slab
        load_row(sx + (10 + q) * ROWF, x, b, t + 1, h0 + q, tid);

    // ---- skip-channel passthrough (independent of smem) ----
    {
        for (int j = tid; j < ROWS * WW * 8; j += THREADS) {   // 8 float4 = 32 skip ch
            int f4  = j & 7;
            int pos = j >> 3;
            int row = pos >> 5;
            int w   = pos & 31;
            size_t gi = ((((size_t)b * TT + t) * HH + h0 + row) * WW + w) * CC + CM;
            ((float4*)(out + gi))[f4] = ((const float4*)(x + gi))[f4];
        }
    }

    __syncthreads();

    // ---- compute: each thread = 1 position x 16 output channels ----
    const int pos    = tid >> 1;
    const int cobase = (tid & 1) * 16;
    const int row    = pos >> 5;
    const int w      = pos & 31;

    int xoff[7];
    xoff[0] = (6 + row)  * ROWF + (w + 1);   // t-1
    xoff[1] = (10 + row) * ROWF + (w + 1);   // t+1
    xoff[2] = row        * ROWF + (w + 1);   // h-1
    xoff[3] = (row + 2)  * ROWF + (w + 1);   // h+1
    xoff[4] = (row + 1)  * ROWF + (w);       // w-1
    xoff[5] = (row + 1)  * ROWF + (w + 2);   // w+1
    xoff[6] = (row + 1)  * ROWF + (w + 1);   // center (combined)

    float acc[16];
#pragma unroll
    for (int j = 0; j < 16; ++j) acc[j] = 0.0f;

#pragma unroll
    for (int tap = 0; tap < 7; ++tap) {
        const float* xp = sx + xoff[tap];
        const float* wp = sw + tap * 1024 + cobase;
#pragma unroll 8
        for (int ci = 0; ci < 32; ++ci) {
            float v = xp[ci * 34];
            const float4* w4 = (const float4*)(wp + ci * 32);
            float4 w0 = w4[0], w1 = w4[1], w2 = w4[2], w3 = w4[3];
            acc[0]  += v * w0.x; acc[1]  += v * w0.y; acc[2]  += v * w0.z; acc[3]  += v * w0.w;
            acc[4]  += v * w1.x; acc[5]  += v * w1.y; acc[6]  += v * w1.z; acc[7]  += v * w1.w;
            acc[8]  += v * w2.x; acc[9]  += v * w2.y; acc[10] += v * w2.z; acc[11] += v * w2.w;
            acc[12] += v * w3.x; acc[13] += v * w3.y; acc[14] += v * w3.z; acc[15] += v * w3.w;
        }
    }

    // ---- ReLU + store ----
#pragma unroll
    for (int j = 0; j < 16; ++j) acc[j] = fmaxf(acc[j], 0.0f);

    size_t go = ((((size_t)b * TT + t) * HH + h0 + row) * WW + w) * CC + cobase;
    float4* o4 = (float4*)(out + go);
    o4[0] = make_float4(acc[0],  acc[1],  acc[2],  acc[3]);
    o4[1] = make_float4(acc[4],  acc[5],  acc[6],  acc[7]);
    o4[2] = make_float4(acc[8],  acc[9],  acc[10], acc[11]);
    o4[3] = make_float4(acc[12], acc[13], acc[14], acc[15]);
}

extern "C" void kernel_launch(void* const* d_in, const int* in_sizes, int n_in,
                              void* d_out, int out_size) {
    const float* x  = (const float*)d_in[0];
    const float* wT = (const float*)d_in[1];
    const float* wH = (const float*)d_in[2];
    const float* wW = (const float*)d_in[3];
    float* out = (float*)d_out;

    const int smem_bytes = SMEM_FLOATS * (int)sizeof(float);   // 89600 B
    cudaFuncSetAttribute(mvf_kernel, cudaFuncAttributeMaxDynamicSharedMemorySize, smem_bytes);

    const int grid = BB * TT * (HH / ROWS);   // 2560 blocks
    mvf_kernel<<<grid, THREADS, smem_bytes>>>(x, wT, wH, wW, out);
}

// round 3
// speedup vs baseline: 1.3373x; 1.3373x over previous
#include <cuda_runtime.h>
#include <cstddef>

// Problem constants
#define BB 8
#define TT 40
#define HH 32
#define WW 32
#define CC 64
#define CM 32
#define HBLK 8
#define THREADS 256

typedef unsigned long long ull;

// Shared layout (floats):
//   center slab: 10 h-rows (h0-1..h0+8), transposed [ci][pos -1..32], pitch 34
//   t-1 slab:     8 h-rows (h0..h0+7),   transposed [ci][pos 0..31],  pitch 33 (no W halo)
//   t+1 slab:     8 h-rows, same
#define CROW (32 * 34)            // 1088 floats per center row
#define TROW (32 * 33)            // 1056 floats per t-slab row
#define OFF_T0 (10 * CROW)        // 10880
#define OFF_T1 (OFF_T0 + 8 * TROW)
#define SMEM_FLOATS (OFF_T1 + 8 * TROW)   // 27776 floats = 111104 B

// Precombined weights: [tap][ci][co], tap order:
// 0:t-1  1:t+1  2:h-1  3:h+1  4:w-1  5:w+1  6:center(sum of 3 centers)
// MUST be 16B-aligned: hot loop uses ld.global.nc.v2.b64 (16B vector loads).
__device__ __align__(16) float g_wc[7 * 32 * 32];

__global__ void combine_w(const float* __restrict__ wT,
                          const float* __restrict__ wH,
                          const float* __restrict__ wW) {
    int tap = blockIdx.x;          // 7 blocks x 1024 threads
    int r   = threadIdx.x;         // index within 32x32 tile
    float v;
    switch (tap) {
        case 0: v = wT[r];            break;
        case 1: v = wT[2048 + r];     break;
        case 2: v = wH[r];            break;
        case 3: v = wH[2048 + r];     break;
        case 4: v = wW[r];            break;
        case 5: v = wW[2048 + r];     break;
        default: v = wT[1024 + r] + wH[1024 + r] + wW[1024 + r]; break;
    }
    g_wc[tap * 1024 + r] = v;
}

// ---- packed f32x2 helpers ----
__device__ __forceinline__ ull dup2(float v) {
    ull r;
    asm("mov.b64 %0, {%1, %1};" : "=l"(r) : "f"(v));
    return r;
}
__device__ __forceinline__ void fma2(ull& d, ull a, ull b) {
    asm("fma.rn.f32x2 %0, %1, %2, %0;" : "+l"(d) : "l"(a), "l"(b));
}
__device__ __forceinline__ void ldg_w4(const float* p, ull& a, ull& b) {
    asm("ld.global.nc.v2.b64 {%0, %1}, [%2];" : "=l"(a), "=l"(b) : "l"(p));
}
__device__ __forceinline__ void unpack2(ull v, float& lo, float& hi) {
    asm("mov.b64 {%0, %1}, %2;" : "=f"(lo), "=f"(hi) : "l"(v));
}

// One tap: 4 positions x 8 co (4 packed pairs), weights from gmem (L1-resident)
__device__ __forceinline__ void tap_fma(ull acc[4][4], const float* wp,
                                        ull x0, ull x1, ull x2, ull x3) {
    ull w0, w1, w2, w3;
    ldg_w4(wp, w0, w1);          // co..co+3
    ldg_w4(wp + 4, w2, w3);      // co+4..co+7
    fma2(acc[0][0], x0, w0); fma2(acc[0][1], x0, w1); fma2(acc[0][2], x0, w2); fma2(acc[0][3], x0, w3);
    fma2(acc[1][0], x1, w0); fma2(acc[1][1], x1, w1); fma2(acc[1][2], x1, w2); fma2(acc[1][3], x1, w3);
    fma2(acc[2][0], x2, w0); fma2(acc[2][1], x2, w1); fma2(acc[2][2], x2, w2); fma2(acc[2][3], x2, w3);
    fma2(acc[3][0], x3, w0); fma2(acc[3][1], x3, w1); fma2(acc[3][2], x3, w2); fma2(acc[3][3], x3, w3);
}

__global__ __launch_bounds__(THREADS, 2)
void mvf2_kernel(const float* __restrict__ x, float* __restrict__ out) {
    extern __shared__ float smem[];
    float* sc  = smem;
    float* st0 = smem + OFF_T0;
    float* st1 = smem + OFF_T1;

    const int tid = threadIdx.x;
    const int bx  = blockIdx.x;
    const int ht  = bx & 3;                 // 4 h-tiles of 8
    const int tmp = bx >> 2;
    const int t   = tmp % TT;
    const int b   = tmp / TT;
    const int h0  = ht * HBLK;

    const int ci = tid & 31;
    const int ws = tid >> 5;

    // ---- center slab: 10 rows with W halos, pitch 34 ----
#pragma unroll
    for (int r = 0; r < 10; ++r) {
        float* dst = sc + r * CROW;
        int h = h0 - 1 + r;
        if (h < 0 || h >= HH) {
            for (int j = tid; j < CROW; j += THREADS) dst[j] = 0.0f;
        } else {
            if (tid < 64) dst[(tid & 31) * 34 + (tid >> 5) * 33] = 0.0f;  // W halos
            const float* src = x + ((((size_t)b * TT + t) * HH + h) * (size_t)WW) * CC;
#pragma unroll
            for (int p = 0; p < 4; ++p) {
                int w = ws + p * 8;
                dst[ci * 34 + w + 1] = src[(size_t)w * CC + ci];
            }
        }
    }

    // ---- t-1 / t+1 slabs: 8 rows, pitch 33, no W halo ----
#pragma unroll
    for (int s = 0; s < 2; ++s) {
        int ts = t + (s ? 1 : -1);
        float* slab = s ? st1 : st0;
        if (ts < 0 || ts >= TT) {
            for (int j = tid; j < 8 * TROW; j += THREADS) slab[j] = 0.0f;
        } else {
#pragma unroll
            for (int r = 0; r < 8; ++r) {
                const float* src = x + ((((size_t)b * TT + ts) * HH + (h0 + r)) * (size_t)WW) * CC;
                float* dst = slab + r * TROW;
#pragma unroll
                for (int p = 0; p < 4; ++p) {
                    int w = ws + p * 8;
                    dst[ci * 33 + w] = src[(size_t)w * CC + ci];
                }
            }
        }
    }

    // ---- skip-channel passthrough (8 rows x 32 w x 32 ch) ----
    for (int j = tid; j < HBLK * WW * 8; j += THREADS) {
        int f4  = j & 7;
        int pos = j >> 3;
        int row = pos >> 5;
        int w   = pos & 31;
        size_t gi = ((((size_t)b * TT + t) * HH + h0 + row) * WW + w) * CC + CM;
        ((float4*)(out + gi))[f4] = ((const float4*)(x + gi))[f4];
    }

    __syncthreads();

    // ---- compute: thread = 4 consecutive w positions x 8 output channels ----
    const int cb = tid & 3;                 // co block
    const int pg = tid >> 2;                // position group
    const int wg = pg & 7;
    const int hr = pg >> 3;                 // h row within tile
    const int w4 = wg * 4;
    const int co = cb * 8;

    const float* pc  = sc  + (hr + 1) * CROW + w4;       // + ci*34 + j : covers w4-1..w4+4
    const float* ph0 = sc  + hr       * CROW + w4 + 1;   // h-1 row, w4..w4+3
    const float* ph1 = sc  + (hr + 2) * CROW + w4 + 1;   // h+1 row
    const float* pt0 = st0 + hr * TROW + w4;             // t-1 row
    const float* pt1 = st1 + hr * TROW + w4;             // t+1 row
    const float* Wg  = g_wc + co;

    ull acc[4][4];
#pragma unroll
    for (int p = 0; p < 4; ++p)
#pragma unroll
        for (int q = 0; q < 4; ++q) acc[p][q] = 0ull;

#pragma unroll 2
    for (int c = 0; c < 32; ++c) {
        const int oc = c * 34;
        const int ot = c * 33;
        // x values for this input channel
        float xc0 = pc[oc + 0], xc1 = pc[oc + 1], xc2 = pc[oc + 2];
        float xc3 = pc[oc + 3], xc4 = pc[oc + 4], xc5 = pc[oc + 5];
        float a0 = pt0[ot + 0], a1 = pt0[ot + 1], a2 = pt0[ot + 2], a3 = pt0[ot + 3];
        float e0 = pt1[ot + 0], e1 = pt1[ot + 1], e2 = pt1[ot + 2], e3 = pt1[ot + 3];
        float g0 = ph0[oc + 0], g1 = ph0[oc + 1], g2 = ph0[oc + 2], g3 = ph0[oc + 3];
        float d0 = ph1[oc + 0], d1 = ph1[oc + 1], d2 = ph1[oc + 2], d3 = ph1[oc + 3];

        const float* wp = Wg + c * 32;
        ull c1 = dup2(xc1), c2 = dup2(xc2), c3 = dup2(xc3), c4 = dup2(xc4);

        tap_fma(acc, wp + 0 * 1024, dup2(a0), dup2(a1), dup2(a2), dup2(a3)); // t-1
        tap_fma(acc, wp + 1 * 1024, dup2(e0), dup2(e1), dup2(e2), dup2(e3)); // t+1
        tap_fma(acc, wp + 2 * 1024, dup2(g0), dup2(g1), dup2(g2), dup2(g3)); // h-1
        tap_fma(acc, wp + 3 * 1024, dup2(d0), dup2(d1), dup2(d2), dup2(d3)); // h+1
        tap_fma(acc, wp + 4 * 1024, dup2(xc0), c1, c2, c3);                  // w-1
        tap_fma(acc, wp + 5 * 1024, c2, c3, c4, dup2(xc5));                  // w+1
        tap_fma(acc, wp + 6 * 1024, c1, c2, c3, c4);                         // center
    }

    // ---- ReLU + store ----
#pragma unroll
    for (int p = 0; p < 4; ++p) {
        float v[8];
#pragma unroll
        for (int q = 0; q < 4; ++q) {
            float lo, hi;
            unpack2(acc[p][q], lo, hi);
            v[2 * q]     = fmaxf(lo, 0.0f);
            v[2 * q + 1] = fmaxf(hi, 0.0f);
        }
        size_t go = ((((size_t)b * TT + t) * HH + h0 + hr) * WW + (w4 + p)) * CC + co;
        float4* o4 = (float4*)(out + go);
        o4[0] = make_float4(v[0], v[1], v[2], v[3]);
        o4[1] = make_float4(v[4], v[5], v[6], v[7]);
    }
}

extern "C" void kernel_launch(void* const* d_in, const int* in_sizes, int n_in,
                              void* d_out, int out_size) {
    const float* x  = (const float*)d_in[0];
    const float* wT = (const float*)d_in[1];
    const float* wH = (const float*)d_in[2];
    const float* wW = (const float*)d_in[3];
    float* out = (float*)d_out;

    combine_w<<<7, 1024>>>(wT, wH, wW);

    const int smem_bytes = SMEM_FLOATS * (int)sizeof(float);   // 111104 B
    cudaFuncSetAttribute(mvf2_kernel, cudaFuncAttributeMaxDynamicSharedMemorySize, smem_bytes);
    const int grid = BB * TT * (HH / HBLK);   // 1280 blocks
    mvf2_kernel<<<grid, THREADS, smem_bytes>>>(x, out);
}